// round 3
// baseline (speedup 1.0000x reference)
#include <cuda_runtime.h>
#include <cuda_bf16.h>

#define NN 50000
#define NE 800000
#define HID 64
#define NB 49   // scan blocks: ceil(50000/1024)

// ---------------- scratch (device globals; no allocation allowed) -------------
__device__ float g_bufA[NN * HID];
__device__ float g_bufB[NN * HID];
__device__ float g_z[NN];
__device__ float g_dinv[NN];
__device__ int   g_cnt[NN];
__device__ int   g_rowptr[NN + 1];
__device__ int   g_fill[NN];
__device__ int   g_col[NE];
__device__ float g_wt[NE];
__device__ int   g_bsum[NB];
__device__ int   g_boff[NB];

// ---------------- CSR build --------------------------------------------------
__global__ void k_zero_cnt() {
    int i = blockIdx.x * blockDim.x + threadIdx.x;
    if (i < NN) g_cnt[i] = 0;
}

__global__ void k_count(const int* __restrict__ ei) {
    int e = blockIdx.x * blockDim.x + threadIdx.x;
    if (e < NE) atomicAdd(&g_cnt[ei[NE + e]], 1);
}

__global__ void k_dinv() {
    int i = blockIdx.x * blockDim.x + threadIdx.x;
    if (i < NN) g_dinv[i] = rsqrtf((float)(g_cnt[i] + 1));  // +1 self loop
}

// pass 1: per-1024-chunk sums (grid NB, block 256; 4 elems/thread)
__global__ void k_blocksum() {
    __shared__ int sw[8];
    int base = blockIdx.x * 1024 + threadIdx.x * 4;
    int v = 0;
    #pragma unroll
    for (int k = 0; k < 4; k++) {
        int i = base + k;
        if (i < NN) v += g_cnt[i];
    }
    #pragma unroll
    for (int o = 16; o; o >>= 1) v += __shfl_xor_sync(0xffffffffu, v, o);
    if ((threadIdx.x & 31) == 0) sw[threadIdx.x >> 5] = v;
    __syncthreads();
    if (threadIdx.x == 0) {
        int s = 0;
        #pragma unroll
        for (int w = 0; w < 8; w++) s += sw[w];
        g_bsum[blockIdx.x] = s;
    }
}

// pass 2: serial exclusive scan of NB partials (trivial)
__global__ void k_scanb() {
    int s = 0;
    for (int b = 0; b < NB; b++) { g_boff[b] = s; s += g_bsum[b]; }
    g_rowptr[NN] = s;
}

// pass 3: per-chunk exclusive scan via shuffles + block offset
__global__ void k_scanfinal() {
    __shared__ int swarp[32];
    int lane = threadIdx.x & 31, wid = threadIdx.x >> 5;
    int i = blockIdx.x * 1024 + threadIdx.x;
    int v = (i < NN) ? g_cnt[i] : 0;
    int incl = v;
    #pragma unroll
    for (int o = 1; o < 32; o <<= 1) {
        int t = __shfl_up_sync(0xffffffffu, incl, o);
        if (lane >= o) incl += t;
    }
    if (lane == 31) swarp[wid] = incl;
    __syncthreads();
    if (wid == 0) {
        int s = swarp[lane];
        int si = s;
        #pragma unroll
        for (int o = 1; o < 32; o <<= 1) {
            int t = __shfl_up_sync(0xffffffffu, si, o);
            if (lane >= o) si += t;
        }
        swarp[lane] = si - s;  // exclusive warp offsets
    }
    __syncthreads();
    if (i < NN) {
        int excl = incl - v + swarp[wid] + g_boff[blockIdx.x];
        g_rowptr[i] = excl;
        g_fill[i]   = excl;
    }
}

__global__ void k_scatter(const int* __restrict__ ei) {
    int e = blockIdx.x * blockDim.x + threadIdx.x;
    if (e < NE) {
        int s = ei[e];
        int d = ei[NE + e];
        int pos = atomicAdd(&g_fill[d], 1);
        g_col[pos] = s;
        g_wt[pos]  = g_dinv[s] * g_dinv[d];
    }
}

// ---------------- layer 0: aggregate x (4-wide) then fused GEMM ---------------
// y[n,0:4] = sum_e w_e * x[src_e,:] + dinv[n]^2 * x[n,:]   -> bufA (stride 4)
__global__ void k_agg_x(const float* __restrict__ x) {
    int n = blockIdx.x * blockDim.x + threadIdx.x;
    if (n >= NN) return;
    const float4* x4 = (const float4*)x;
    float4 acc = make_float4(0.f, 0.f, 0.f, 0.f);
    int beg = g_rowptr[n], end = g_rowptr[n + 1];
    for (int j = beg; j < end; j++) {
        int s = g_col[j];
        float w = g_wt[j];
        float4 v = __ldg(&x4[s]);
        acc.x = fmaf(w, v.x, acc.x);
        acc.y = fmaf(w, v.y, acc.y);
        acc.z = fmaf(w, v.z, acc.z);
        acc.w = fmaf(w, v.w, acc.w);
    }
    float di = g_dinv[n], ws = di * di;
    float4 sv = x4[n];
    acc.x = fmaf(ws, sv.x, acc.x);
    acc.y = fmaf(ws, sv.y, acc.y);
    acc.z = fmaf(ws, sv.z, acc.z);
    acc.w = fmaf(ws, sv.w, acc.w);
    ((float4*)g_bufA)[n] = acc;
}

// h0 = relu( y[NN,4] @ W_in[4,64] + b )  -> bufB
__global__ void k_gemm_in(const float* __restrict__ W, const float* __restrict__ bias) {
    __shared__ float Ws[4 * HID];
    __shared__ float Bs[HID];
    if (threadIdx.x < 256) Ws[threadIdx.x] = W[threadIdx.x];
    if (threadIdx.x < HID) Bs[threadIdx.x] = bias[threadIdx.x];
    __syncthreads();
    int t = blockIdx.x * blockDim.x + threadIdx.x;
    int n = t >> 6, f = t & 63;
    if (n < NN) {
        float4 y = ((const float4*)g_bufA)[n];
        float acc = Bs[f];
        acc = fmaf(y.x, Ws[0 * HID + f], acc);
        acc = fmaf(y.y, Ws[1 * HID + f], acc);
        acc = fmaf(y.z, Ws[2 * HID + f], acc);
        acc = fmaf(y.w, Ws[3 * HID + f], acc);
        g_bufB[n * HID + f] = fmaxf(acc, 0.f);
    }
}

// ---------------- hidden dense: bufB @ W -> bufA ------------------------------
__global__ void k_gemm64(const float* __restrict__ W) {
    __shared__ float Ws[HID * HID];
    __shared__ float Hs[4 * HID];
    for (int i = threadIdx.x; i < HID * HID; i += blockDim.x) Ws[i] = W[i];
    int nodeBase = blockIdx.x * 64;
    int f  = threadIdx.x & 63;
    int nl = threadIdx.x >> 6;
    for (int c = 0; c < 64; c += 4) {
        __syncthreads();
        int n = nodeBase + c + nl;
        Hs[nl * HID + f] = (n < NN) ? g_bufB[n * HID + f] : 0.f;
        __syncthreads();
        if (n < NN) {
            float acc = 0.f;
            #pragma unroll
            for (int k = 0; k < HID; k++) acc = fmaf(Hs[nl * HID + k], Ws[k * HID + f], acc);
            g_bufA[n * HID + f] = acc;
        }
    }
}

// ---------------- hidden aggregation: warp/node, float4, 2 edges/iter ---------
__global__ void k_agg64(const float* __restrict__ bias) {
    int warp = (blockIdx.x * blockDim.x + threadIdx.x) >> 5;
    int lane = threadIdx.x & 31;
    if (warp >= NN) return;
    int n = warp;
    int half = lane >> 4, fl = lane & 15;
    const float4* A4 = (const float4*)g_bufA;
    float4 acc = make_float4(0.f, 0.f, 0.f, 0.f);
    int beg = g_rowptr[n], end = g_rowptr[n + 1];
    for (int j = beg + half; j < end; j += 2) {
        int s = g_col[j];
        float w = g_wt[j];
        float4 v = __ldg(&A4[s * 16 + fl]);
        acc.x = fmaf(w, v.x, acc.x);
        acc.y = fmaf(w, v.y, acc.y);
        acc.z = fmaf(w, v.z, acc.z);
        acc.w = fmaf(w, v.w, acc.w);
    }
    acc.x += __shfl_xor_sync(0xffffffffu, acc.x, 16);
    acc.y += __shfl_xor_sync(0xffffffffu, acc.y, 16);
    acc.z += __shfl_xor_sync(0xffffffffu, acc.z, 16);
    acc.w += __shfl_xor_sync(0xffffffffu, acc.w, 16);
    if (half == 0) {
        float di = g_dinv[n], ws = di * di;
        float4 sv = A4[n * 16 + fl];
        float4 b4 = ((const float4*)bias)[fl];
        acc.x = fmaxf(fmaf(ws, sv.x, acc.x) + b4.x, 0.f);
        acc.y = fmaxf(fmaf(ws, sv.y, acc.y) + b4.y, 0.f);
        acc.z = fmaxf(fmaf(ws, sv.z, acc.z) + b4.z, 0.f);
        acc.w = fmaxf(fmaf(ws, sv.w, acc.w) + b4.w, 0.f);
        ((float4*)g_bufB)[n * 16 + fl] = acc;
    }
}

// ---------------- output layer ------------------------------------------------
__global__ void k_gemm_out(const float* __restrict__ Wout) {
    int warp = (blockIdx.x * blockDim.x + threadIdx.x) >> 5;
    int lane = threadIdx.x & 31;
    if (warp < NN) {
        float a = g_bufB[warp * HID + lane] * Wout[lane]
                + g_bufB[warp * HID + lane + 32] * Wout[lane + 32];
        #pragma unroll
        for (int o = 16; o; o >>= 1) a += __shfl_xor_sync(0xffffffffu, a, o);
        if (lane == 0) g_z[warp] = a;
    }
}

__global__ void k_agg_scalar(float* __restrict__ out, const float* __restrict__ b_out) {
    int n = blockIdx.x * blockDim.x + threadIdx.x;
    if (n < NN) {
        float acc = 0.f;
        int beg = g_rowptr[n], end = g_rowptr[n + 1];
        for (int j = beg; j < end; j++) acc = fmaf(g_wt[j], __ldg(&g_z[g_col[j]]), acc);
        float di = g_dinv[n];
        acc = fmaf(di * di, g_z[n], acc);
        out[n] = acc + b_out[0];
    }
}

// ---------------- launch ------------------------------------------------------
extern "C" void kernel_launch(void* const* d_in, const int* in_sizes, int n_in,
                              void* d_out, int out_size) {
    const float* x     = (const float*)d_in[0];
    const int*   ei    = (const int*)d_in[1];
    const float* W_in  = (const float*)d_in[2];
    const float* b_in  = (const float*)d_in[3];
    const float* W_h   = (const float*)d_in[4];
    const float* b_h   = (const float*)d_in[5];
    const float* W_out = (const float*)d_in[6];
    const float* b_out = (const float*)d_in[7];
    float*       out   = (float*)d_out;

    const int TB = 256;
    const int gN  = (NN + TB - 1) / TB;
    const int gE  = (NE + TB - 1) / TB;
    const int gNF = (NN * HID + TB - 1) / TB;
    const int gW  = (NN * 32 + TB - 1) / TB;
    const int gG  = (NN + 63) / 64;

    // CSR build
    k_zero_cnt<<<gN, TB>>>();
    k_count<<<gE, TB>>>(ei);
    k_dinv<<<gN, TB>>>();
    k_blocksum<<<NB, 256>>>();
    k_scanb<<<1, 1>>>();
    k_scanfinal<<<NB, 1024>>>();
    k_scatter<<<gE, TB>>>(ei);

    // layer 0: aggregate x (4-wide), then fused gemm+bias+relu
    k_agg_x<<<gN, TB>>>(x);
    k_gemm_in<<<gNF, TB>>>(W_in, b_in);

    // hidden layers
    for (int l = 0; l < 3; l++) {
        k_gemm64<<<gG, TB>>>(W_h + l * HID * HID);
        k_agg64<<<gW, TB>>>(b_h + l * HID);
    }

    // output layer
    k_gemm_out<<<gW, TB>>>(W_out);
    k_agg_scalar<<<gN, TB>>>(out, b_out);
}

// round 4
// speedup vs baseline: 1.5279x; 1.5279x over previous
#include <cuda_runtime.h>
#include <cuda_bf16.h>

#define NN 50000
#define NE 800000
#define HID 64
#define NB 49   // scan blocks: ceil(50000/1024)

// ---------------- scratch (device globals; no allocation allowed) -------------
__device__ float g_bufA[NN * HID];
__device__ float g_bufB[NN * HID];
__device__ float g_z[NN];
__device__ float g_dinv[NN];
__device__ int   g_cnt[NN];
__device__ int   g_rowptr[NN + 1];
__device__ int   g_fill[NN];
__device__ int   g_col[NE];
__device__ float g_wt[NE];
__device__ int   g_bsum[NB];
__device__ int   g_boff[NB];

// ---------------- CSR build --------------------------------------------------
__global__ void k_zero_cnt() {
    int i = blockIdx.x * blockDim.x + threadIdx.x;
    if (i < NN) g_cnt[i] = 0;
}

__global__ void k_count(const int* __restrict__ ei) {
    int e = blockIdx.x * blockDim.x + threadIdx.x;
    if (e < NE) atomicAdd(&g_cnt[ei[NE + e]], 1);
}

__global__ void k_dinv() {
    int i = blockIdx.x * blockDim.x + threadIdx.x;
    if (i < NN) g_dinv[i] = rsqrtf((float)(g_cnt[i] + 1));  // +1 self loop
}

// pass 1: per-1024-chunk sums
__global__ void k_blocksum() {
    __shared__ int sw[8];
    int base = blockIdx.x * 1024 + threadIdx.x * 4;
    int v = 0;
    #pragma unroll
    for (int k = 0; k < 4; k++) {
        int i = base + k;
        if (i < NN) v += g_cnt[i];
    }
    #pragma unroll
    for (int o = 16; o; o >>= 1) v += __shfl_xor_sync(0xffffffffu, v, o);
    if ((threadIdx.x & 31) == 0) sw[threadIdx.x >> 5] = v;
    __syncthreads();
    if (threadIdx.x == 0) {
        int s = 0;
        #pragma unroll
        for (int w = 0; w < 8; w++) s += sw[w];
        g_bsum[blockIdx.x] = s;
    }
}

// pass 2: serial exclusive scan of NB partials
__global__ void k_scanb() {
    int s = 0;
    for (int b = 0; b < NB; b++) { g_boff[b] = s; s += g_bsum[b]; }
    g_rowptr[NN] = s;
}

// pass 3: per-chunk exclusive scan via shuffles + block offset
__global__ void k_scanfinal() {
    __shared__ int swarp[32];
    int lane = threadIdx.x & 31, wid = threadIdx.x >> 5;
    int i = blockIdx.x * 1024 + threadIdx.x;
    int v = (i < NN) ? g_cnt[i] : 0;
    int incl = v;
    #pragma unroll
    for (int o = 1; o < 32; o <<= 1) {
        int t = __shfl_up_sync(0xffffffffu, incl, o);
        if (lane >= o) incl += t;
    }
    if (lane == 31) swarp[wid] = incl;
    __syncthreads();
    if (wid == 0) {
        int s = swarp[lane];
        int si = s;
        #pragma unroll
        for (int o = 1; o < 32; o <<= 1) {
            int t = __shfl_up_sync(0xffffffffu, si, o);
            if (lane >= o) si += t;
        }
        swarp[lane] = si - s;
    }
    __syncthreads();
    if (i < NN) {
        int excl = incl - v + swarp[wid] + g_boff[blockIdx.x];
        g_rowptr[i] = excl;
        g_fill[i]   = excl;
    }
}

__global__ void k_scatter(const int* __restrict__ ei) {
    int e = blockIdx.x * blockDim.x + threadIdx.x;
    if (e < NE) {
        int s = ei[e];
        int d = ei[NE + e];
        int pos = atomicAdd(&g_fill[d], 1);
        g_col[pos] = s;
        g_wt[pos]  = g_dinv[s] * g_dinv[d];
    }
}

// ---------------- layer 0: aggregate raw x (4-wide), warp/node, edge-parallel --
__global__ void k_agg_x(const float* __restrict__ x) {
    int warp = (blockIdx.x * blockDim.x + threadIdx.x) >> 5;
    int lane = threadIdx.x & 31;
    if (warp >= NN) return;
    int n = warp;
    const float4* x4 = (const float4*)x;
    float4 acc = make_float4(0.f, 0.f, 0.f, 0.f);
    int beg = g_rowptr[n], end = g_rowptr[n + 1];
    for (int j = beg + lane; j < end; j += 32) {
        int s = g_col[j];
        float w = g_wt[j];
        float4 v = __ldg(&x4[s]);
        acc.x = fmaf(w, v.x, acc.x);
        acc.y = fmaf(w, v.y, acc.y);
        acc.z = fmaf(w, v.z, acc.z);
        acc.w = fmaf(w, v.w, acc.w);
    }
    #pragma unroll
    for (int o = 16; o; o >>= 1) {
        acc.x += __shfl_xor_sync(0xffffffffu, acc.x, o);
        acc.y += __shfl_xor_sync(0xffffffffu, acc.y, o);
        acc.z += __shfl_xor_sync(0xffffffffu, acc.z, o);
        acc.w += __shfl_xor_sync(0xffffffffu, acc.w, o);
    }
    if (lane == 0) {
        float di = g_dinv[n], ws = di * di;
        float4 sv = x4[n];
        acc.x = fmaf(ws, sv.x, acc.x);
        acc.y = fmaf(ws, sv.y, acc.y);
        acc.z = fmaf(ws, sv.z, acc.z);
        acc.w = fmaf(ws, sv.w, acc.w);
        ((float4*)g_bufA)[n] = acc;
    }
}

// h0 = relu( y[NN,4] @ W_in[4,64] + b )  -> bufB
__global__ void k_gemm_in(const float* __restrict__ W, const float* __restrict__ bias) {
    __shared__ float Ws[4 * HID];
    __shared__ float Bs[HID];
    if (threadIdx.x < 256) Ws[threadIdx.x] = W[threadIdx.x];
    if (threadIdx.x < HID) Bs[threadIdx.x] = bias[threadIdx.x];
    __syncthreads();
    int t = blockIdx.x * blockDim.x + threadIdx.x;
    int n = t >> 6, f = t & 63;
    if (n < NN) {
        float4 y = ((const float4*)g_bufA)[n];
        float acc = Bs[f];
        acc = fmaf(y.x, Ws[0 * HID + f], acc);
        acc = fmaf(y.y, Ws[1 * HID + f], acc);
        acc = fmaf(y.z, Ws[2 * HID + f], acc);
        acc = fmaf(y.w, Ws[3 * HID + f], acc);
        g_bufB[n * HID + f] = fmaxf(acc, 0.f);
    }
}

// ---------------- hidden dense: bufB @ W -> bufA ------------------------------
__global__ void k_gemm64(const float* __restrict__ W) {
    __shared__ float Ws[HID * HID];
    __shared__ float Hs[4 * HID];
    for (int i = threadIdx.x; i < HID * HID; i += blockDim.x) Ws[i] = W[i];
    int nodeBase = blockIdx.x * 64;
    int f  = threadIdx.x & 63;
    int nl = threadIdx.x >> 6;
    for (int c = 0; c < 64; c += 4) {
        __syncthreads();
        int n = nodeBase + c + nl;
        Hs[nl * HID + f] = (n < NN) ? g_bufB[n * HID + f] : 0.f;
        __syncthreads();
        if (n < NN) {
            float acc = 0.f;
            #pragma unroll
            for (int k = 0; k < HID; k++) acc = fmaf(Hs[nl * HID + k], Ws[k * HID + f], acc);
            g_bufA[n * HID + f] = acc;
        }
    }
}

// ---------------- hidden aggregation: warp/node, scalar lanes (R2 form) -------
__global__ void k_agg64(const float* __restrict__ bias) {
    int warp = (blockIdx.x * blockDim.x + threadIdx.x) >> 5;
    int lane = threadIdx.x & 31;
    if (warp >= NN) return;
    int n = warp;
    float a0 = 0.f, a1 = 0.f;
    int beg = g_rowptr[n], end = g_rowptr[n + 1];
    for (int j = beg; j < end; j++) {
        int s = g_col[j];
        float w = g_wt[j];
        a0 = fmaf(w, __ldg(&g_bufA[s * HID + lane]), a0);
        a1 = fmaf(w, __ldg(&g_bufA[s * HID + lane + 32]), a1);
    }
    float di = g_dinv[n], ws = di * di;
    a0 = fmaf(ws, g_bufA[n * HID + lane],      a0) + bias[lane];
    a1 = fmaf(ws, g_bufA[n * HID + lane + 32], a1) + bias[lane + 32];
    a0 = fmaxf(a0, 0.f);
    a1 = fmaxf(a1, 0.f);
    g_bufB[n * HID + lane]      = a0;
    g_bufB[n * HID + lane + 32] = a1;
}

// ---------------- output layer ------------------------------------------------
__global__ void k_gemm_out(const float* __restrict__ Wout) {
    int warp = (blockIdx.x * blockDim.x + threadIdx.x) >> 5;
    int lane = threadIdx.x & 31;
    if (warp < NN) {
        float a = g_bufB[warp * HID + lane] * Wout[lane]
                + g_bufB[warp * HID + lane + 32] * Wout[lane + 32];
        #pragma unroll
        for (int o = 16; o; o >>= 1) a += __shfl_xor_sync(0xffffffffu, a, o);
        if (lane == 0) g_z[warp] = a;
    }
}

__global__ void k_agg_scalar(float* __restrict__ out, const float* __restrict__ b_out) {
    int n = blockIdx.x * blockDim.x + threadIdx.x;
    if (n < NN) {
        float acc = 0.f;
        int beg = g_rowptr[n], end = g_rowptr[n + 1];
        for (int j = beg; j < end; j++) acc = fmaf(g_wt[j], __ldg(&g_z[g_col[j]]), acc);
        float di = g_dinv[n];
        acc = fmaf(di * di, g_z[n], acc);
        out[n] = acc + b_out[0];
    }
}

// ---------------- launch ------------------------------------------------------
extern "C" void kernel_launch(void* const* d_in, const int* in_sizes, int n_in,
                              void* d_out, int out_size) {
    const float* x     = (const float*)d_in[0];
    const int*   ei    = (const int*)d_in[1];
    const float* W_in  = (const float*)d_in[2];
    const float* b_in  = (const float*)d_in[3];
    const float* W_h   = (const float*)d_in[4];
    const float* b_h   = (const float*)d_in[5];
    const float* W_out = (const float*)d_in[6];
    const float* b_out = (const float*)d_in[7];
    float*       out   = (float*)d_out;

    const int TB = 256;
    const int gN  = (NN + TB - 1) / TB;
    const int gE  = (NE + TB - 1) / TB;
    const int gNF = (NN * HID + TB - 1) / TB;
    const int gW  = (NN * 32 + TB - 1) / TB;
    const int gG  = (NN + 63) / 64;

    // CSR build
    k_zero_cnt<<<gN, TB>>>();
    k_count<<<gE, TB>>>(ei);
    k_dinv<<<gN, TB>>>();
    k_blocksum<<<NB, 256>>>();
    k_scanb<<<1, 1>>>();
    k_scanfinal<<<NB, 1024>>>();
    k_scatter<<<gE, TB>>>(ei);

    // layer 0: aggregate x (4-wide, warp/node), then fused gemm+bias+relu
    k_agg_x<<<gW, TB>>>(x);
    k_gemm_in<<<gNF, TB>>>(W_in, b_in);

    // hidden layers
    for (int l = 0; l < 3; l++) {
        k_gemm64<<<gG, TB>>>(W_h + l * HID * HID);
        k_agg64<<<gW, TB>>>(b_h + l * HID);
    }

    // output layer
    k_gemm_out<<<gW, TB>>>(W_out);
    k_agg_scalar<<<gN, TB>>>(out, b_out);
}